// round 1
// baseline (speedup 1.0000x reference)
#include <cuda_runtime.h>
#include <math.h>

#define BATCH 16384
#define DIM   512
#define HID   2048

#define BM 128
#define BN 128
#define BK 16

// Scratch (static __device__ — allocation-free per harness rules)
__device__ float g_h1[BATCH * HID];   // 128 MB
__device__ float g_h2[BATCH * HID];   // 128 MB
__device__ float g_dh1[BATCH * HID];  // 128 MB
__device__ float g_g[BATCH * DIM];    // 32 MB
__device__ float g_v3[HID];

enum { TA_NONE = 0, TA_V3 = 1, TA_DH = 2 };
enum { EPI_NONE = 0, EPI_BIAS = 1, EPI_BIAS_TANH = 2 };

// v3[j] = sum_i W3[i, j]  (cotangent of ones through W3)
__global__ void k_v3(const float* __restrict__ W3) {
    int j = blockIdx.x * blockDim.x + threadIdx.x;
    float s = 0.f;
#pragma unroll 8
    for (int i = 0; i < DIM; ++i) s += W3[i * HID + j];
    g_v3[j] = s;
}

// C[M,N] = epi( transform(A)[M,K] * B )   — B_NT: B is [N,K] (C=A*B^T); else B is [K,N]
// TA_V3: a = v3[k] * (1 - a*a)            (a is h2; produces d2 on the fly)
// TA_DH: a = a * (1 - h*h), h = A2 at same index (a is dh1, h is h1; produces d1)
template <int TA, int EPI, bool B_NT>
__global__ __launch_bounds__(256, 2) void gemm_kernel(
    const float* __restrict__ A, int lda,
    const float* __restrict__ A2,
    const float* __restrict__ B, int ldb,
    const float* __restrict__ bias,
    float* __restrict__ C, int ldc,
    int K)
{
    __shared__ float As[BK][BM];
    __shared__ float Bs[BK][BN];

    const int tid = threadIdx.x;
    const int m0 = blockIdx.y * BM;
    const int n0 = blockIdx.x * BN;
    const int tx = tid & 15;   // n sub-tile
    const int ty = tid >> 4;   // m sub-tile

    unsigned long long acc[8][4];  // 8 rows x 4 f32x2 pairs (8 cols)
#pragma unroll
    for (int i = 0; i < 8; ++i)
#pragma unroll
        for (int j = 0; j < 4; ++j) acc[i][j] = 0ull;

    for (int k0 = 0; k0 < K; k0 += BK) {
        // A tile -> As[k][m]  (warp: consecutive m, same k: conflict-free STS, L1-friendly LDG)
#pragma unroll
        for (int i = 0; i < 8; ++i) {
            int idx = tid + i * 256;
            int r = idx & 127;
            int c = idx >> 7;
            float v = A[(size_t)(m0 + r) * lda + k0 + c];
            if (TA == TA_V3) {
                v = g_v3[k0 + c] * (1.f - v * v);
            } else if (TA == TA_DH) {
                float h = A2[(size_t)(m0 + r) * lda + k0 + c];
                v = v * (1.f - h * h);
            }
            As[c][r] = v;
        }
        // B tile -> Bs[k][n]
#pragma unroll
        for (int i = 0; i < 8; ++i) {
            int idx = tid + i * 256;
            int n = idx & 127;
            int c = idx >> 7;
            float v;
            if (B_NT) v = B[(size_t)(n0 + n) * ldb + k0 + c];
            else      v = B[(size_t)(k0 + c) * ldb + n0 + n];
            Bs[c][n] = v;
        }
        __syncthreads();

#pragma unroll
        for (int kk = 0; kk < BK; ++kk) {
            float4 a0 = *reinterpret_cast<const float4*>(&As[kk][ty * 8]);
            float4 a1 = *reinterpret_cast<const float4*>(&As[kk][ty * 8 + 4]);
            unsigned long long b[4];
#pragma unroll
            for (int j = 0; j < 4; ++j)
                b[j] = *reinterpret_cast<const unsigned long long*>(&Bs[kk][tx * 8 + j * 2]);
            float a[8] = {a0.x, a0.y, a0.z, a0.w, a1.x, a1.y, a1.z, a1.w};
#pragma unroll
            for (int i = 0; i < 8; ++i) {
                unsigned long long ad;
                unsigned int au = __float_as_uint(a[i]);
                asm("mov.b64 %0, {%1, %1};" : "=l"(ad) : "r"(au));
#pragma unroll
                for (int j = 0; j < 4; ++j) {
                    // packed dual-fp32 FMA: 2x fp32 rate on sm_103a
                    asm("fma.rn.f32x2 %0, %1, %2, %0;"
                        : "+l"(acc[i][j]) : "l"(ad), "l"(b[j]));
                }
            }
        }
        __syncthreads();
    }

    const int cm = m0 + ty * 8;
    const int cn = n0 + tx * 8;
#pragma unroll
    for (int i = 0; i < 8; ++i) {
#pragma unroll
        for (int j = 0; j < 4; ++j) {
            float vx = __uint_as_float((unsigned int)(acc[i][j] & 0xFFFFFFFFull));
            float vy = __uint_as_float((unsigned int)(acc[i][j] >> 32));
            int n = cn + j * 2;
            if (EPI != EPI_NONE) { vx += bias[n]; vy += bias[n + 1]; }
            if (EPI == EPI_BIAS_TANH) { vx = tanhf(vx); vy = tanhf(vy); }
            C[(size_t)(cm + i) * ldc + n]     = vx;
            C[(size_t)(cm + i) * ldc + n + 1] = vy;
        }
    }
}

// trace[b] = (1/3) * sum_k dot(eps[k,b,:], g[b,:]) -> out[b, 512]
__global__ void k_trace(const float* __restrict__ eps, float* __restrict__ out) {
    int gw = (blockIdx.x * blockDim.x + threadIdx.x) >> 5;  // one warp per row
    int lane = threadIdx.x & 31;
    const float* g  = g_g + (size_t)gw * DIM;
    const float* e0 = eps + (size_t)gw * DIM;
    const float* e1 = eps + ((size_t)BATCH + gw) * DIM;
    const float* e2 = eps + ((size_t)2 * BATCH + gw) * DIM;
    float s = 0.f;
    for (int d = lane * 4; d < DIM; d += 128) {
        float4 gv = *(const float4*)(g + d);
        float4 a  = *(const float4*)(e0 + d);
        float4 b  = *(const float4*)(e1 + d);
        float4 c  = *(const float4*)(e2 + d);
        s += gv.x * (a.x + b.x + c.x) + gv.y * (a.y + b.y + c.y)
           + gv.z * (a.z + b.z + c.z) + gv.w * (a.w + b.w + c.w);
    }
#pragma unroll
    for (int off = 16; off; off >>= 1) s += __shfl_xor_sync(0xFFFFFFFFu, s, off);
    if (lane == 0) out[(size_t)gw * (DIM + 1) + DIM] = s * (1.f / 3.f);
}

extern "C" void kernel_launch(void* const* d_in, const int* in_sizes, int n_in,
                              void* d_out, int out_size) {
    // metadata order: t, augmented_state, epsilons, W1, b1, W2, b2, W3, b3
    const float* aug = (const float*)d_in[1];
    const float* eps = (const float*)d_in[2];
    const float* W1  = (const float*)d_in[3];
    const float* b1  = (const float*)d_in[4];
    const float* W2  = (const float*)d_in[5];
    const float* b2  = (const float*)d_in[6];
    const float* W3  = (const float*)d_in[7];
    const float* b3  = (const float*)d_in[8];
    float* out = (float*)d_out;

    float *h1, *h2, *dh1, *gg;
    cudaGetSymbolAddress((void**)&h1,  g_h1);
    cudaGetSymbolAddress((void**)&h2,  g_h2);
    cudaGetSymbolAddress((void**)&dh1, g_dh1);
    cudaGetSymbolAddress((void**)&gg,  g_g);

    dim3 blk(256);

    k_v3<<<HID / 256, 256>>>(W3);

    // h1 = tanh(z @ W1^T + b1)        [16384,512]x[2048,512]^T
    gemm_kernel<TA_NONE, EPI_BIAS_TANH, true>
        <<<dim3(HID / BN, BATCH / BM), blk>>>(aug, DIM + 1, nullptr, W1, DIM, b1, h1, HID, DIM);

    // h2 = tanh(h1 @ W2^T + b2)
    gemm_kernel<TA_NONE, EPI_BIAS_TANH, true>
        <<<dim3(HID / BN, BATCH / BM), blk>>>(h1, HID, nullptr, W2, HID, b2, h2, HID, HID);

    // dz_dt = h2 @ W3^T + b3  -> out[:, :512]  (row stride 513)
    gemm_kernel<TA_NONE, EPI_BIAS, true>
        <<<dim3(DIM / BN, BATCH / BM), blk>>>(h2, HID, nullptr, W3, HID, b3, out, DIM + 1, HID);

    // dh1 = (v3 * (1 - h2^2)) @ W2    (mask fused into A load)
    gemm_kernel<TA_V3, EPI_NONE, false>
        <<<dim3(HID / BN, BATCH / BM), blk>>>(h2, HID, nullptr, W2, HID, nullptr, dh1, HID, HID);

    // g = (dh1 * (1 - h1^2)) @ W1     (mask fused into A load)
    gemm_kernel<TA_DH, EPI_NONE, false>
        <<<dim3(DIM / BN, BATCH / BM), blk>>>(dh1, HID, h1, W1, DIM, nullptr, gg, DIM, HID);

    // trace column
    k_trace<<<BATCH / 8, 256>>>(eps, out);
}

// round 3
// speedup vs baseline: 4.4631x; 4.4631x over previous
#include <cuda_runtime.h>
#include <cuda_bf16.h>
#include <math.h>
#include <stdint.h>

#define BATCH 16384
#define DIM   512
#define HID   2048

#define BM 128
#define BN 128
#define BK 32
#define THREADS 256

// smem: padded rows 40 bf16 = 80B (conflict-free ldmatrix, 16B-aligned for cp.async)
#define ROWB   80
#define OA_H   0
#define OA_L   10240
#define OB_H   20480
#define OB_L   30720
#define STAGE  40960
#define SMEM_TOTAL (2 * STAGE)

// ---------------- scratch (allocation-free) ----------------
__device__ float g_h1[(size_t)BATCH * HID];
__device__ float g_h2[(size_t)BATCH * HID];
__device__ float g_dh1[(size_t)BATCH * HID];
__device__ float g_g[(size_t)BATCH * DIM];
__device__ float g_z[(size_t)BATCH * DIM];
__device__ float g_v3[HID];
__device__ __nv_bfloat16 g_W1h[HID * DIM],  g_W1l[HID * DIM];
__device__ __nv_bfloat16 g_W2h[HID * HID],  g_W2l[HID * HID];
__device__ __nv_bfloat16 g_W3h[DIM * HID],  g_W3l[DIM * HID];
__device__ __nv_bfloat16 g_W2Th[HID * HID], g_W2Tl[HID * HID];
__device__ __nv_bfloat16 g_W1Th[DIM * HID], g_W1Tl[DIM * HID];

enum { TA_NONE = 0, TA_V3 = 1, TA_DH = 2 };
enum { EPI_NONE = 0, EPI_BIAS = 1, EPI_BIAS_TANH = 2 };

// ---------------- helpers ----------------
__device__ __forceinline__ uint32_t s2u(const void* p) {
    uint32_t a;
    asm("{ .reg .u64 t; cvta.to.shared.u64 t, %1; cvt.u32.u64 %0, t; }" : "=r"(a) : "l"(p));
    return a;
}

__device__ __forceinline__ void ldsm4(uint32_t* r, uint32_t addr) {
    asm volatile("ldmatrix.sync.aligned.m8n8.x4.shared.b16 {%0,%1,%2,%3}, [%4];"
                 : "=r"(r[0]), "=r"(r[1]), "=r"(r[2]), "=r"(r[3]) : "r"(addr));
}

__device__ __forceinline__ void mma16816(float* c, const uint32_t* a, const uint32_t* b) {
    asm volatile("mma.sync.aligned.m16n8k16.row.col.f32.bf16.bf16.f32 "
                 "{%0,%1,%2,%3}, {%4,%5,%6,%7}, {%8,%9}, {%0,%1,%2,%3};"
                 : "+f"(c[0]), "+f"(c[1]), "+f"(c[2]), "+f"(c[3])
                 : "r"(a[0]), "r"(a[1]), "r"(a[2]), "r"(a[3]), "r"(b[0]), "r"(b[1]));
}

__device__ __forceinline__ void cp16(uint32_t dst, const void* src) {
    asm volatile("cp.async.ca.shared.global [%0], [%1], 16;" :: "r"(dst), "l"(src) : "memory");
}

__device__ __forceinline__ float ftanh(float x) {
    float e = __expf(2.f * x);
    return 1.f - __fdividef(2.f, e + 1.f);
}

// ---------------- A prefetch/split ----------------
struct APre { float4 v[4]; float4 h[4]; };

template <int TA>
__device__ __forceinline__ void ldgA(APre& p, const float* __restrict__ A,
                                     const float* __restrict__ A2,
                                     int lda, int m0, int k0, int tid) {
#pragma unroll
    for (int i = 0; i < 4; ++i) {
        int f = tid + i * 256;
        int row = f >> 3, c4 = f & 7;
        size_t go = (size_t)(m0 + row) * lda + k0 + c4 * 4;
        p.v[i] = *reinterpret_cast<const float4*>(A + go);
        if (TA == TA_DH) p.h[i] = *reinterpret_cast<const float4*>(A2 + go);
        if (TA == TA_V3) p.h[i] = *reinterpret_cast<const float4*>(g_v3 + k0 + c4 * 4);
    }
}

template <int TA>
__device__ __forceinline__ void stsA(const APre& p, char* dh, char* dl, int tid) {
#pragma unroll
    for (int i = 0; i < 4; ++i) {
        int f = tid + i * 256;
        int row = f >> 3, c4 = f & 7;
        float4 v = p.v[i];
        if (TA == TA_V3) {
            float4 s = p.h[i];
            v.x = s.x * (1.f - v.x * v.x); v.y = s.y * (1.f - v.y * v.y);
            v.z = s.z * (1.f - v.z * v.z); v.w = s.w * (1.f - v.w * v.w);
        } else if (TA == TA_DH) {
            float4 h = p.h[i];
            v.x *= (1.f - h.x * h.x); v.y *= (1.f - h.y * h.y);
            v.z *= (1.f - h.z * h.z); v.w *= (1.f - h.w * h.w);
        }
        __nv_bfloat162 h0 = __floats2bfloat162_rn(v.x, v.y);
        __nv_bfloat162 h1 = __floats2bfloat162_rn(v.z, v.w);
        __nv_bfloat162 l0 = __floats2bfloat162_rn(v.x - __bfloat162float(h0.x),
                                                  v.y - __bfloat162float(h0.y));
        __nv_bfloat162 l1 = __floats2bfloat162_rn(v.z - __bfloat162float(h1.x),
                                                  v.w - __bfloat162float(h1.y));
        int off = row * ROWB + c4 * 8;
        unsigned long long hv = (unsigned long long)*(uint32_t*)&h0 |
                                ((unsigned long long)*(uint32_t*)&h1 << 32);
        unsigned long long lv = (unsigned long long)*(uint32_t*)&l0 |
                                ((unsigned long long)*(uint32_t*)&l1 << 32);
        *reinterpret_cast<unsigned long long*>(dh + off) = hv;
        *reinterpret_cast<unsigned long long*>(dl + off) = lv;
    }
}

__device__ __forceinline__ void cpB(uint32_t dstBase, const __nv_bfloat16* __restrict__ src,
                                    int K, int n0, int k0, int tid) {
#pragma unroll
    for (int i = 0; i < 2; ++i) {
        int idx = tid + i * 256;
        int row = idx >> 2, seg = idx & 3;
        cp16(dstBase + row * ROWB + seg * 16,
             src + (size_t)(n0 + row) * K + k0 + seg * 8);
    }
}

// ---------------- split-bf16 warp-MMA GEMM ----------------
// C[M,N] = epi( transform(A)[M,K] * B[N,K]^T ),  A=Ah+Al, B=Bh+Bl (3 MMA terms)
template <int TA, int EPI>
__global__ void __launch_bounds__(THREADS) mma_gemm(
    const float* __restrict__ A, int lda, const float* __restrict__ A2,
    const __nv_bfloat16* __restrict__ Bh, const __nv_bfloat16* __restrict__ Bl,
    const float* __restrict__ bias, float* __restrict__ C, int ldc, int K)
{
    extern __shared__ char smem[];
    const uint32_t sb = s2u(smem);
    const int tid = threadIdx.x, lane = tid & 31, wid = tid >> 5;
    const int wm = wid >> 2, wn = wid & 3;           // 2 x 4 warp grid, 64x32 per warp
    const int m0 = blockIdx.y * BM, n0 = blockIdx.x * BN;
    const int NC = K >> 5;

    float acc[4][4][4];
#pragma unroll
    for (int a = 0; a < 4; ++a)
#pragma unroll
        for (int b = 0; b < 4; ++b)
#pragma unroll
            for (int c = 0; c < 4; ++c) acc[a][b][c] = 0.f;

    // ldmatrix per-lane byte offsets
    const int aRow = lane & 15;
    const int aKh = (lane >> 4) * 16;                 // +8 elems = 16B
    const int bRow = (lane & 7) + ((lane >> 4) << 3);
    const int bKh = ((lane >> 3) & 1) * 16;
    uint32_t aOff[4], bOff[2];
#pragma unroll
    for (int mb = 0; mb < 4; ++mb) aOff[mb] = (wm * 64 + mb * 16 + aRow) * ROWB + aKh;
#pragma unroll
    for (int pr = 0; pr < 2; ++pr) bOff[pr] = (wn * 32 + pr * 16 + bRow) * ROWB + bKh;

    // prologue: chunk 0 -> stage 0
    APre p;
    ldgA<TA>(p, A, A2, lda, m0, 0, tid);
    cpB(sb + OB_H, Bh, K, n0, 0, tid);
    cpB(sb + OB_L, Bl, K, n0, 0, tid);
    asm volatile("cp.async.commit_group;" ::: "memory");
    stsA<TA>(p, smem + OA_H, smem + OA_L, tid);
    asm volatile("cp.async.wait_group 0;" ::: "memory");
    __syncthreads();

    for (int c = 0; c < NC; ++c) {
        const int s = c & 1;
        const uint32_t st = sb + s * STAGE;
        char* nxt = smem + (s ^ 1) * STAGE;
        const bool pre = (c + 1 < NC);
        if (pre) {
            ldgA<TA>(p, A, A2, lda, m0, (c + 1) * BK, tid);
            cpB(sb + (s ^ 1) * STAGE + OB_H, Bh, K, n0, (c + 1) * BK, tid);
            cpB(sb + (s ^ 1) * STAGE + OB_L, Bl, K, n0, (c + 1) * BK, tid);
            asm volatile("cp.async.commit_group;" ::: "memory");
        }
#pragma unroll
        for (int ks = 0; ks < 2; ++ks) {
            uint32_t ah[4][4], al[4][4], bh[2][4], bl[2][4];
#pragma unroll
            for (int mb = 0; mb < 4; ++mb) ldsm4(ah[mb], st + OA_H + aOff[mb] + ks * 32);
#pragma unroll
            for (int mb = 0; mb < 4; ++mb) ldsm4(al[mb], st + OA_L + aOff[mb] + ks * 32);
#pragma unroll
            for (int pr = 0; pr < 2; ++pr) ldsm4(bh[pr], st + OB_H + bOff[pr] + ks * 32);
#pragma unroll
            for (int pr = 0; pr < 2; ++pr) ldsm4(bl[pr], st + OB_L + bOff[pr] + ks * 32);
#pragma unroll
            for (int mb = 0; mb < 4; ++mb)
#pragma unroll
                for (int nb = 0; nb < 4; ++nb) {
                    const uint32_t* fh = &bh[nb >> 1][(nb & 1) * 2];
                    const uint32_t* fl = &bl[nb >> 1][(nb & 1) * 2];
                    mma16816(acc[mb][nb], ah[mb], fh);
                    mma16816(acc[mb][nb], ah[mb], fl);
                    mma16816(acc[mb][nb], al[mb], fh);
                }
        }
        if (pre) {
            stsA<TA>(p, nxt + OA_H, nxt + OA_L, tid);
            asm volatile("cp.async.wait_group 0;" ::: "memory");
        }
        __syncthreads();
    }

    // epilogue
    const int g = lane >> 2, tg = lane & 3;
    const bool vec = ((ldc & 1) == 0);
#pragma unroll
    for (int mb = 0; mb < 4; ++mb) {
#pragma unroll
        for (int nb = 0; nb < 4; ++nb) {
            float* cc = acc[mb][nb];
            int r0 = m0 + wm * 64 + mb * 16 + g;
            int col = n0 + wn * 32 + nb * 8 + tg * 2;
            if (EPI != EPI_NONE) {
                float bx = __ldg(bias + col), by = __ldg(bias + col + 1);
                cc[0] += bx; cc[1] += by; cc[2] += bx; cc[3] += by;
                if (EPI == EPI_BIAS_TANH) {
                    cc[0] = ftanh(cc[0]); cc[1] = ftanh(cc[1]);
                    cc[2] = ftanh(cc[2]); cc[3] = ftanh(cc[3]);
                }
            }
            if (vec) {
                *reinterpret_cast<float2*>(C + (size_t)r0 * ldc + col) = make_float2(cc[0], cc[1]);
                *reinterpret_cast<float2*>(C + (size_t)(r0 + 8) * ldc + col) = make_float2(cc[2], cc[3]);
            } else {
                C[(size_t)r0 * ldc + col] = cc[0];
                C[(size_t)r0 * ldc + col + 1] = cc[1];
                C[(size_t)(r0 + 8) * ldc + col] = cc[2];
                C[(size_t)(r0 + 8) * ldc + col + 1] = cc[3];
            }
        }
    }
}

// ---------------- prep / misc kernels ----------------
__global__ void k_pack_z(const float* __restrict__ aug) {
    int b = blockIdx.x;
    g_z[(size_t)b * DIM + threadIdx.x] = aug[(size_t)b * (DIM + 1) + threadIdx.x];
}

__global__ void k_split(const float* __restrict__ W, __nv_bfloat16* __restrict__ hi,
                        __nv_bfloat16* __restrict__ lo, int n) {
    int i = blockIdx.x * blockDim.x + threadIdx.x;
    if (i < n) {
        float v = W[i];
        __nv_bfloat16 h = __float2bfloat16(v);
        hi[i] = h;
        lo[i] = __float2bfloat16(v - __bfloat162float(h));
    }
}

__global__ void k_splitT(const float* __restrict__ in, __nv_bfloat16* __restrict__ hi,
                         __nv_bfloat16* __restrict__ lo, int K, int Nn) {
    int k = blockIdx.x * blockDim.x + threadIdx.x;
    int n = blockIdx.y;
    float v = in[(size_t)k * Nn + n];
    __nv_bfloat16 h = __float2bfloat16(v);
    hi[(size_t)n * K + k] = h;
    lo[(size_t)n * K + k] = __float2bfloat16(v - __bfloat162float(h));
}

__global__ void k_v3(const float* __restrict__ W3) {
    int j = blockIdx.x * blockDim.x + threadIdx.x;
    float s = 0.f;
#pragma unroll 8
    for (int i = 0; i < DIM; ++i) s += W3[(size_t)i * HID + j];
    g_v3[j] = s;
}

__global__ void k_trace(const float* __restrict__ eps, float* __restrict__ out) {
    int gw = (blockIdx.x * blockDim.x + threadIdx.x) >> 5;
    int lane = threadIdx.x & 31;
    const float* g  = g_g + (size_t)gw * DIM;
    const float* e0 = eps + (size_t)gw * DIM;
    const float* e1 = eps + ((size_t)BATCH + gw) * DIM;
    const float* e2 = eps + ((size_t)2 * BATCH + gw) * DIM;
    float s = 0.f;
    for (int d = lane * 4; d < DIM; d += 128) {
        float4 gv = *(const float4*)(g + d);
        float4 a  = *(const float4*)(e0 + d);
        float4 b  = *(const float4*)(e1 + d);
        float4 c  = *(const float4*)(e2 + d);
        s += gv.x * (a.x + b.x + c.x) + gv.y * (a.y + b.y + c.y)
           + gv.z * (a.z + b.z + c.z) + gv.w * (a.w + b.w + c.w);
    }
#pragma unroll
    for (int off = 16; off; off >>= 1) s += __shfl_xor_sync(0xFFFFFFFFu, s, off);
    if (lane == 0) out[(size_t)gw * (DIM + 1) + DIM] = s * (1.f / 3.f);
}

// ---------------- launch ----------------
extern "C" void kernel_launch(void* const* d_in, const int* in_sizes, int n_in,
                              void* d_out, int out_size) {
    const float* aug = (const float*)d_in[1];
    const float* eps = (const float*)d_in[2];
    const float* W1  = (const float*)d_in[3];
    const float* b1  = (const float*)d_in[4];
    const float* W2  = (const float*)d_in[5];
    const float* b2  = (const float*)d_in[6];
    const float* W3  = (const float*)d_in[7];
    const float* b3  = (const float*)d_in[8];
    float* out = (float*)d_out;

    float *h1, *h2, *dh1, *gg, *zz;
    cudaGetSymbolAddress((void**)&h1,  g_h1);
    cudaGetSymbolAddress((void**)&h2,  g_h2);
    cudaGetSymbolAddress((void**)&dh1, g_dh1);
    cudaGetSymbolAddress((void**)&gg,  g_g);
    cudaGetSymbolAddress((void**)&zz,  g_z);
    __nv_bfloat16 *w1h, *w1l, *w2h, *w2l, *w3h, *w3l, *w2th, *w2tl, *w1th, *w1tl;
    cudaGetSymbolAddress((void**)&w1h,  g_W1h);  cudaGetSymbolAddress((void**)&w1l,  g_W1l);
    cudaGetSymbolAddress((void**)&w2h,  g_W2h);  cudaGetSymbolAddress((void**)&w2l,  g_W2l);
    cudaGetSymbolAddress((void**)&w3h,  g_W3h);  cudaGetSymbolAddress((void**)&w3l,  g_W3l);
    cudaGetSymbolAddress((void**)&w2th, g_W2Th); cudaGetSymbolAddress((void**)&w2tl, g_W2Tl);
    cudaGetSymbolAddress((void**)&w1th, g_W1Th); cudaGetSymbolAddress((void**)&w1tl, g_W1Tl);

    cudaFuncSetAttribute(mma_gemm<TA_NONE, EPI_BIAS_TANH>, cudaFuncAttributeMaxDynamicSharedMemorySize, SMEM_TOTAL);
    cudaFuncSetAttribute(mma_gemm<TA_NONE, EPI_BIAS>,      cudaFuncAttributeMaxDynamicSharedMemorySize, SMEM_TOTAL);
    cudaFuncSetAttribute(mma_gemm<TA_V3,   EPI_NONE>,      cudaFuncAttributeMaxDynamicSharedMemorySize, SMEM_TOTAL);
    cudaFuncSetAttribute(mma_gemm<TA_DH,   EPI_NONE>,      cudaFuncAttributeMaxDynamicSharedMemorySize, SMEM_TOTAL);

    // prep
    k_pack_z<<<BATCH, DIM>>>(aug);
    k_split<<<(HID * DIM + 255) / 256, 256>>>(W1, w1h, w1l, HID * DIM);
    k_split<<<(HID * HID + 255) / 256, 256>>>(W2, w2h, w2l, HID * HID);
    k_split<<<(DIM * HID + 255) / 256, 256>>>(W3, w3h, w3l, DIM * HID);
    k_splitT<<<dim3(HID / 256, DIM), 256>>>(W1, w1th, w1tl, HID, DIM);   // W1^T [512,2048]
    k_splitT<<<dim3(HID / 256, HID), 256>>>(W2, w2th, w2tl, HID, HID);   // W2^T [2048,2048]
    k_v3<<<HID / 256, 256>>>(W3);

    // h1 = tanh(z @ W1^T + b1)
    mma_gemm<TA_NONE, EPI_BIAS_TANH><<<dim3(HID / BN, BATCH / BM), THREADS, SMEM_TOTAL>>>(
        zz, DIM, nullptr, w1h, w1l, b1, h1, HID, DIM);
    // h2 = tanh(h1 @ W2^T + b2)
    mma_gemm<TA_NONE, EPI_BIAS_TANH><<<dim3(HID / BN, BATCH / BM), THREADS, SMEM_TOTAL>>>(
        h1, HID, nullptr, w2h, w2l, b2, h2, HID, HID);
    // dz_dt = h2 @ W3^T + b3 -> out[:, :512] (ldc = 513)
    mma_gemm<TA_NONE, EPI_BIAS><<<dim3(DIM / BN, BATCH / BM), THREADS, SMEM_TOTAL>>>(
        h2, HID, nullptr, w3h, w3l, b3, out, DIM + 1, HID);
    // dh1 = (v3 * (1 - h2^2)) @ W2   (B = W2^T as [N,K])
    mma_gemm<TA_V3, EPI_NONE><<<dim3(HID / BN, BATCH / BM), THREADS, SMEM_TOTAL>>>(
        h2, HID, nullptr, w2th, w2tl, nullptr, dh1, HID, HID);
    // g = (dh1 * (1 - h1^2)) @ W1    (B = W1^T as [N,K])
    mma_gemm<TA_DH, EPI_NONE><<<dim3(DIM / BN, BATCH / BM), THREADS, SMEM_TOTAL>>>(
        dh1, HID, h1, w1th, w1tl, nullptr, gg, DIM, HID);

    k_trace<<<BATCH / 8, 256>>>(eps, out);
}

// round 4
// speedup vs baseline: 4.9645x; 1.1123x over previous
#include <cuda_runtime.h>
#include <cuda_bf16.h>
#include <math.h>
#include <stdint.h>

#define BATCH 16384
#define DIM   512
#define HID   2048

#define BM 128
#define BN 128
#define BK 32
#define THREADS 256

// smem rows padded to 80B (32 bf16 + 16B pad): conflict-free ldmatrix phases
#define ROWB   80
#define OA_H   0
#define OA_L   10240
#define OB_H   20480
#define OB_L   30720
#define STAGE  40960
#define SMEM_TOTAL (2 * STAGE)

// ---------------- scratch (allocation-free) ----------------
__device__ __nv_bfloat16 g_zh[(size_t)BATCH * DIM],  g_zl[(size_t)BATCH * DIM];
__device__ __nv_bfloat16 g_h1h[(size_t)BATCH * HID], g_h1l[(size_t)BATCH * HID];
__device__ __nv_bfloat16 g_h2h[(size_t)BATCH * HID], g_h2l[(size_t)BATCH * HID];
__device__ __nv_bfloat16 g_d2h[(size_t)BATCH * HID], g_d2l[(size_t)BATCH * HID];
__device__ __nv_bfloat16 g_d1h[(size_t)BATCH * HID], g_d1l[(size_t)BATCH * HID];
__device__ float g_g[(size_t)BATCH * DIM];
__device__ float g_v3[HID];
__device__ __nv_bfloat16 g_W1h[HID * DIM],  g_W1l[HID * DIM];
__device__ __nv_bfloat16 g_W2h[HID * HID],  g_W2l[HID * HID];
__device__ __nv_bfloat16 g_W3h[DIM * HID],  g_W3l[DIM * HID];
__device__ __nv_bfloat16 g_W2Th[HID * HID], g_W2Tl[HID * HID];
__device__ __nv_bfloat16 g_W1Th[DIM * HID], g_W1Tl[DIM * HID];

enum { EPI_H1 = 0, EPI_H2D2 = 1, EPI_OUT = 2, EPI_D1 = 3, EPI_G = 4 };

// ---------------- helpers ----------------
__device__ __forceinline__ uint32_t s2u(const void* p) {
    uint32_t a;
    asm("{ .reg .u64 t; cvta.to.shared.u64 t, %1; cvt.u32.u64 %0, t; }" : "=r"(a) : "l"(p));
    return a;
}

__device__ __forceinline__ void ldsm4(uint32_t* r, uint32_t addr) {
    asm volatile("ldmatrix.sync.aligned.m8n8.x4.shared.b16 {%0,%1,%2,%3}, [%4];"
                 : "=r"(r[0]), "=r"(r[1]), "=r"(r[2]), "=r"(r[3]) : "r"(addr));
}

__device__ __forceinline__ void mma16816(float* c, const uint32_t* a, const uint32_t* b) {
    asm volatile("mma.sync.aligned.m16n8k16.row.col.f32.bf16.bf16.f32 "
                 "{%0,%1,%2,%3}, {%4,%5,%6,%7}, {%8,%9}, {%0,%1,%2,%3};"
                 : "+f"(c[0]), "+f"(c[1]), "+f"(c[2]), "+f"(c[3])
                 : "r"(a[0]), "r"(a[1]), "r"(a[2]), "r"(a[3]), "r"(b[0]), "r"(b[1]));
}

__device__ __forceinline__ void cp16(uint32_t dst, const void* src) {
    asm volatile("cp.async.cg.shared.global [%0], [%1], 16;" :: "r"(dst), "l"(src) : "memory");
}

__device__ __forceinline__ float ftanh(float x) {
    float e = __expf(2.f * x);
    return 1.f - __fdividef(2.f, e + 1.f);
}

__device__ __forceinline__ void split_store(__nv_bfloat16* __restrict__ H,
                                            __nv_bfloat16* __restrict__ L,
                                            size_t off, float x, float y) {
    __nv_bfloat162 h = __floats2bfloat162_rn(x, y);
    __nv_bfloat162 l = __floats2bfloat162_rn(x - __bfloat162float(h.x),
                                             y - __bfloat162float(h.y));
    *reinterpret_cast<__nv_bfloat162*>(H + off) = h;
    *reinterpret_cast<__nv_bfloat162*>(L + off) = l;
}

// tile: 128 rows x 32 cols bf16 hi+lo via cp.async (4 transfers/thread)
__device__ __forceinline__ void cpTile(uint32_t dstH, uint32_t dstL,
                                       const __nv_bfloat16* __restrict__ srcH,
                                       const __nv_bfloat16* __restrict__ srcL,
                                       int ld, int r0, int k0, int tid) {
#pragma unroll
    for (int i = 0; i < 2; ++i) {
        int idx = tid + i * 256;
        int row = idx >> 2, seg = idx & 3;
        size_t go = (size_t)(r0 + row) * ld + k0 + seg * 8;
        uint32_t so = row * ROWB + seg * 16;
        cp16(dstH + so, srcH + go);
        cp16(dstL + so, srcL + go);
    }
}

// ---------------- split-bf16 warp-MMA GEMM ----------------
// acc[M,N] = (Ah+Al)[M,K] * ((Bh+Bl)[N,K])^T  (3 terms), epilogue per EPI
template <int EPI>
__global__ void __launch_bounds__(THREADS, 2) mma_gemm(
    const __nv_bfloat16* __restrict__ Ah, const __nv_bfloat16* __restrict__ Al,
    const __nv_bfloat16* __restrict__ Bh, const __nv_bfloat16* __restrict__ Bl,
    const float* __restrict__ bias, const float* __restrict__ v3p,
    float* __restrict__ C, int ldc,
    __nv_bfloat16* __restrict__ P1h, __nv_bfloat16* __restrict__ P1l,
    __nv_bfloat16* __restrict__ P2h, __nv_bfloat16* __restrict__ P2l,
    const __nv_bfloat16* __restrict__ Xh, const __nv_bfloat16* __restrict__ Xl,
    int K, int ldp)
{
    extern __shared__ char smem[];
    const uint32_t sb = s2u(smem);
    const int tid = threadIdx.x, lane = tid & 31, wid = tid >> 5;
    const int wm = wid >> 2, wn = wid & 3;           // 2x4 warps, 64x32 each
    const int m0 = blockIdx.y * BM, n0 = blockIdx.x * BN;
    const int NC = K >> 5;

    float acc[4][4][4];
#pragma unroll
    for (int a = 0; a < 4; ++a)
#pragma unroll
        for (int b = 0; b < 4; ++b)
#pragma unroll
            for (int c = 0; c < 4; ++c) acc[a][b][c] = 0.f;

    const int aRow = lane & 15;
    const int aKh = (lane >> 4) * 16;
    const int bRow = (lane & 7) + ((lane >> 4) << 3);
    const int bKh = ((lane >> 3) & 1) * 16;
    uint32_t aOff[4], bOff[2];
#pragma unroll
    for (int mb = 0; mb < 4; ++mb) aOff[mb] = (wm * 64 + mb * 16 + aRow) * ROWB + aKh;
#pragma unroll
    for (int pr = 0; pr < 2; ++pr) bOff[pr] = (wn * 32 + pr * 16 + bRow) * ROWB + bKh;

    // prologue: chunk 0 -> stage 0
    cpTile(sb + OA_H, sb + OA_L, Ah, Al, K, m0, 0, tid);
    cpTile(sb + OB_H, sb + OB_L, Bh, Bl, K, n0, 0, tid);
    asm volatile("cp.async.commit_group;" ::: "memory");

    for (int c = 0; c < NC; ++c) {
        const int s = c & 1;
        const uint32_t st = sb + s * STAGE;
        __syncthreads();   // everyone done reading stage s^1 (iter c-1)
        if (c + 1 < NC) {
            const uint32_t nx = sb + (s ^ 1) * STAGE;
            cpTile(nx + OA_H, nx + OA_L, Ah, Al, K, m0, (c + 1) * BK, tid);
            cpTile(nx + OB_H, nx + OB_L, Bh, Bl, K, n0, (c + 1) * BK, tid);
        }
        asm volatile("cp.async.commit_group;" ::: "memory");
        asm volatile("cp.async.wait_group 1;" ::: "memory");
        __syncthreads();   // chunk c visible

#pragma unroll
        for (int ks = 0; ks < 2; ++ks) {
            uint32_t ah[4][4], al[4][4], bh[2][4], bl[2][4];
#pragma unroll
            for (int mb = 0; mb < 4; ++mb) ldsm4(ah[mb], st + OA_H + aOff[mb] + ks * 32);
#pragma unroll
            for (int mb = 0; mb < 4; ++mb) ldsm4(al[mb], st + OA_L + aOff[mb] + ks * 32);
#pragma unroll
            for (int pr = 0; pr < 2; ++pr) ldsm4(bh[pr], st + OB_H + bOff[pr] + ks * 32);
#pragma unroll
            for (int pr = 0; pr < 2; ++pr) ldsm4(bl[pr], st + OB_L + bOff[pr] + ks * 32);
#pragma unroll
            for (int mb = 0; mb < 4; ++mb)
#pragma unroll
                for (int nb = 0; nb < 4; ++nb) {
                    const uint32_t* fh = &bh[nb >> 1][(nb & 1) * 2];
                    const uint32_t* fl = &bl[nb >> 1][(nb & 1) * 2];
                    mma16816(acc[mb][nb], ah[mb], fh);
                    mma16816(acc[mb][nb], ah[mb], fl);
                    mma16816(acc[mb][nb], al[mb], fh);
                }
        }
    }

    // ---------------- epilogue ----------------
    const int g = lane >> 2, tg = lane & 3;
#pragma unroll
    for (int mb = 0; mb < 4; ++mb) {
#pragma unroll
        for (int nb = 0; nb < 4; ++nb) {
            float* cc = acc[mb][nb];
            const int r0 = m0 + wm * 64 + mb * 16 + g;
            const int col = n0 + wn * 32 + nb * 8 + tg * 2;
            if (EPI == EPI_H1) {
                float bx = __ldg(bias + col), by = __ldg(bias + col + 1);
                float t0 = ftanh(cc[0] + bx), t1 = ftanh(cc[1] + by);
                float t2 = ftanh(cc[2] + bx), t3 = ftanh(cc[3] + by);
                split_store(P1h, P1l, (size_t)r0 * ldp + col, t0, t1);
                split_store(P1h, P1l, (size_t)(r0 + 8) * ldp + col, t2, t3);
            } else if (EPI == EPI_H2D2) {
                float bx = __ldg(bias + col), by = __ldg(bias + col + 1);
                float vx = __ldg(v3p + col), vy = __ldg(v3p + col + 1);
                float t0 = ftanh(cc[0] + bx), t1 = ftanh(cc[1] + by);
                float t2 = ftanh(cc[2] + bx), t3 = ftanh(cc[3] + by);
                split_store(P1h, P1l, (size_t)r0 * ldp + col, t0, t1);
                split_store(P1h, P1l, (size_t)(r0 + 8) * ldp + col, t2, t3);
                split_store(P2h, P2l, (size_t)r0 * ldp + col,
                            vx * (1.f - t0 * t0), vy * (1.f - t1 * t1));
                split_store(P2h, P2l, (size_t)(r0 + 8) * ldp + col,
                            vx * (1.f - t2 * t2), vy * (1.f - t3 * t3));
            } else if (EPI == EPI_OUT) {
                float bx = __ldg(bias + col), by = __ldg(bias + col + 1);
                C[(size_t)r0 * ldc + col]     = cc[0] + bx;
                C[(size_t)r0 * ldc + col + 1] = cc[1] + by;
                C[(size_t)(r0 + 8) * ldc + col]     = cc[2] + bx;
                C[(size_t)(r0 + 8) * ldc + col + 1] = cc[3] + by;
            } else if (EPI == EPI_D1) {
#pragma unroll
                for (int rr = 0; rr < 2; ++rr) {
                    size_t off = (size_t)(r0 + rr * 8) * ldp + col;
                    __nv_bfloat162 hh = *reinterpret_cast<const __nv_bfloat162*>(Xh + off);
                    __nv_bfloat162 hl = *reinterpret_cast<const __nv_bfloat162*>(Xl + off);
                    float h0 = __bfloat162float(hh.x) + __bfloat162float(hl.x);
                    float h1 = __bfloat162float(hh.y) + __bfloat162float(hl.y);
                    split_store(P1h, P1l, off,
                                cc[rr * 2] * (1.f - h0 * h0),
                                cc[rr * 2 + 1] * (1.f - h1 * h1));
                }
            } else {  // EPI_G
                *reinterpret_cast<float2*>(C + (size_t)r0 * ldc + col) =
                    make_float2(cc[0], cc[1]);
                *reinterpret_cast<float2*>(C + (size_t)(r0 + 8) * ldc + col) =
                    make_float2(cc[2], cc[3]);
            }
        }
    }
}

// ---------------- prep / misc kernels ----------------
__global__ void k_pack_z(const float* __restrict__ aug) {
    int b = blockIdx.x, t = threadIdx.x;
    float v = aug[(size_t)b * (DIM + 1) + t];
    __nv_bfloat16 h = __float2bfloat16(v);
    g_zh[(size_t)b * DIM + t] = h;
    g_zl[(size_t)b * DIM + t] = __float2bfloat16(v - __bfloat162float(h));
}

__global__ void k_split(const float* __restrict__ W, __nv_bfloat16* __restrict__ hi,
                        __nv_bfloat16* __restrict__ lo, int n) {
    int i = blockIdx.x * blockDim.x + threadIdx.x;
    if (i < n) {
        float v = W[i];
        __nv_bfloat16 h = __float2bfloat16(v);
        hi[i] = h;
        lo[i] = __float2bfloat16(v - __bfloat162float(h));
    }
}

__global__ void k_splitT(const float* __restrict__ in, __nv_bfloat16* __restrict__ hi,
                         __nv_bfloat16* __restrict__ lo, int K, int Nn) {
    int k = blockIdx.x * blockDim.x + threadIdx.x;
    int n = blockIdx.y;
    float v = in[(size_t)k * Nn + n];
    __nv_bfloat16 h = __float2bfloat16(v);
    hi[(size_t)n * K + k] = h;
    lo[(size_t)n * K + k] = __float2bfloat16(v - __bfloat162float(h));
}

__global__ void k_v3(const float* __restrict__ W3) {
    int j = blockIdx.x * blockDim.x + threadIdx.x;
    float s = 0.f;
#pragma unroll 8
    for (int i = 0; i < DIM; ++i) s += W3[(size_t)i * HID + j];
    g_v3[j] = s;
}

__global__ void k_trace(const float* __restrict__ eps, float* __restrict__ out) {
    int gw = (blockIdx.x * blockDim.x + threadIdx.x) >> 5;
    int lane = threadIdx.x & 31;
    const float* g  = g_g + (size_t)gw * DIM;
    const float* e0 = eps + (size_t)gw * DIM;
    const float* e1 = eps + ((size_t)BATCH + gw) * DIM;
    const float* e2 = eps + ((size_t)2 * BATCH + gw) * DIM;
    float s = 0.f;
    for (int d = lane * 4; d < DIM; d += 128) {
        float4 gv = *(const float4*)(g + d);
        float4 a  = *(const float4*)(e0 + d);
        float4 b  = *(const float4*)(e1 + d);
        float4 c  = *(const float4*)(e2 + d);
        s += gv.x * (a.x + b.x + c.x) + gv.y * (a.y + b.y + c.y)
           + gv.z * (a.z + b.z + c.z) + gv.w * (a.w + b.w + c.w);
    }
#pragma unroll
    for (int off = 16; off; off >>= 1) s += __shfl_xor_sync(0xFFFFFFFFu, s, off);
    if (lane == 0) out[(size_t)gw * (DIM + 1) + DIM] = s * (1.f / 3.f);
}

// ---------------- launch ----------------
extern "C" void kernel_launch(void* const* d_in, const int* in_sizes, int n_in,
                              void* d_out, int out_size) {
    const float* aug = (const float*)d_in[1];
    const float* eps = (const float*)d_in[2];
    const float* W1  = (const float*)d_in[3];
    const float* b1  = (const float*)d_in[4];
    const float* W2  = (const float*)d_in[5];
    const float* b2  = (const float*)d_in[6];
    const float* W3  = (const float*)d_in[7];
    const float* b3  = (const float*)d_in[8];
    float* out = (float*)d_out;

    __nv_bfloat16 *zh, *zl, *h1h, *h1l, *h2h, *h2l, *d2h, *d2l, *d1h, *d1l;
    cudaGetSymbolAddress((void**)&zh,  g_zh);  cudaGetSymbolAddress((void**)&zl,  g_zl);
    cudaGetSymbolAddress((void**)&h1h, g_h1h); cudaGetSymbolAddress((void**)&h1l, g_h1l);
    cudaGetSymbolAddress((void**)&h2h, g_h2h); cudaGetSymbolAddress((void**)&h2l, g_h2l);
    cudaGetSymbolAddress((void**)&d2h, g_d2h); cudaGetSymbolAddress((void**)&d2l, g_d2l);
    cudaGetSymbolAddress((void**)&d1h, g_d1h); cudaGetSymbolAddress((void**)&d1l, g_d1l);
    float *gg, *v3p;
    cudaGetSymbolAddress((void**)&gg,  g_g);
    cudaGetSymbolAddress((void**)&v3p, g_v3);
    __nv_bfloat16 *w1h, *w1l, *w2h, *w2l, *w3h, *w3l, *w2th, *w2tl, *w1th, *w1tl;
    cudaGetSymbolAddress((void**)&w1h,  g_W1h);  cudaGetSymbolAddress((void**)&w1l,  g_W1l);
    cudaGetSymbolAddress((void**)&w2h,  g_W2h);  cudaGetSymbolAddress((void**)&w2l,  g_W2l);
    cudaGetSymbolAddress((void**)&w3h,  g_W3h);  cudaGetSymbolAddress((void**)&w3l,  g_W3l);
    cudaGetSymbolAddress((void**)&w2th, g_W2Th); cudaGetSymbolAddress((void**)&w2tl, g_W2Tl);
    cudaGetSymbolAddress((void**)&w1th, g_W1Th); cudaGetSymbolAddress((void**)&w1tl, g_W1Tl);

    cudaFuncSetAttribute(mma_gemm<EPI_H1>,   cudaFuncAttributeMaxDynamicSharedMemorySize, SMEM_TOTAL);
    cudaFuncSetAttribute(mma_gemm<EPI_H2D2>, cudaFuncAttributeMaxDynamicSharedMemorySize, SMEM_TOTAL);
    cudaFuncSetAttribute(mma_gemm<EPI_OUT>,  cudaFuncAttributeMaxDynamicSharedMemorySize, SMEM_TOTAL);
    cudaFuncSetAttribute(mma_gemm<EPI_D1>,   cudaFuncAttributeMaxDynamicSharedMemorySize, SMEM_TOTAL);
    cudaFuncSetAttribute(mma_gemm<EPI_G>,    cudaFuncAttributeMaxDynamicSharedMemorySize, SMEM_TOTAL);

    // prep
    k_pack_z<<<BATCH, DIM>>>(aug);
    k_split<<<(HID * DIM + 255) / 256, 256>>>(W1, w1h, w1l, HID * DIM);
    k_split<<<(HID * HID + 255) / 256, 256>>>(W2, w2h, w2l, HID * HID);
    k_split<<<(DIM * HID + 255) / 256, 256>>>(W3, w3h, w3l, DIM * HID);
    k_splitT<<<dim3(HID / 256, DIM), 256>>>(W1, w1th, w1tl, HID, DIM);
    k_splitT<<<dim3(HID / 256, HID), 256>>>(W2, w2th, w2tl, HID, HID);
    k_v3<<<HID / 256, 256>>>(W3);

    // G1: h1 = tanh(z @ W1^T + b1)   [K=512]
    mma_gemm<EPI_H1><<<dim3(HID / BN, BATCH / BM), THREADS, SMEM_TOTAL>>>(
        zh, zl, w1h, w1l, b1, nullptr, nullptr, 0,
        h1h, h1l, nullptr, nullptr, nullptr, nullptr, DIM, HID);
    // G2: h2 = tanh(h1 @ W2^T + b2); d2 = v3*(1-h2^2)
    mma_gemm<EPI_H2D2><<<dim3(HID / BN, BATCH / BM), THREADS, SMEM_TOTAL>>>(
        h1h, h1l, w2h, w2l, b2, v3p, nullptr, 0,
        h2h, h2l, d2h, d2l, nullptr, nullptr, HID, HID);
    // G3: dz_dt = h2 @ W3^T + b3 -> out[:, :512] (ldc=513)
    mma_gemm<EPI_OUT><<<dim3(DIM / BN, BATCH / BM), THREADS, SMEM_TOTAL>>>(
        h2h, h2l, w3h, w3l, b3, nullptr, out, DIM + 1,
        nullptr, nullptr, nullptr, nullptr, nullptr, nullptr, HID, 0);
    // G4: dh1 = d2 @ W2; d1 = dh1*(1-h1^2)
    mma_gemm<EPI_D1><<<dim3(HID / BN, BATCH / BM), THREADS, SMEM_TOTAL>>>(
        d2h, d2l, w2th, w2tl, nullptr, nullptr, nullptr, 0,
        d1h, d1l, nullptr, nullptr, h1h, h1l, HID, HID);
    // G5: g = d1 @ W1
    mma_gemm<EPI_G><<<dim3(DIM / BN, BATCH / BM), THREADS, SMEM_TOTAL>>>(
        d1h, d1l, w1th, w1tl, nullptr, nullptr, gg, DIM,
        nullptr, nullptr, nullptr, nullptr, nullptr, nullptr, HID, 0);

    k_trace<<<BATCH / 8, 256>>>(eps, out);
}